// round 3
// baseline (speedup 1.0000x reference)
#include <cuda_runtime.h>
#include <math.h>

#define NN 50000
#define NEDGE 800000
#define ETOT (NEDGE + NN)
#define F 128

// ---- scratch (static device globals; no allocation anywhere) ----
__device__ float g_h[(size_t)NN * F];     // per-layer transformed features
__device__ float g_x2[(size_t)NN * F];    // layer-2 input
__device__ float g_acc[(size_t)NN * F];   // aggregation accumulator (unnormalized)
__device__ float g_as[NN * 8];            // alpha_src per node/head
__device__ float g_ad[NN * 8];            // alpha_dst per node/head
__device__ float g_s[NN * 8];             // unnormalized softmax denominator
__device__ float g_gmax[8];               // global per-head max of g_as

__device__ __forceinline__ float lrelu(float v) { return v >= 0.f ? v : 0.2f * v; }

__device__ __forceinline__ void atomicMaxF(float* a, float v) {
    if (v >= 0.f) atomicMax((int*)a, __float_as_int(v));
    else          atomicMin((unsigned int*)a, __float_as_uint(v));
}

// ---- GEMM h = x @ W, fused alpha_src/alpha_dst epilogue ----
// block = 256 threads (8 warps), 32 rows/block, 4 rows/warp, 4 cols/lane
__global__ void gemm_alpha(const float* __restrict__ xin, int use_x2,
                           const float* __restrict__ W,
                           const float* __restrict__ asr,
                           const float* __restrict__ adr)
{
    const float* x = use_x2 ? g_x2 : xin;
    __shared__ float Wsh[64 * 128];   // 32 KB
    __shared__ float Xsh[32 * 64];    // 8 KB
    int tid  = threadIdx.x;
    int warp = tid >> 5, lane = tid & 31;
    int row0 = blockIdx.x * 32;
    float acc[4][4];
#pragma unroll
    for (int r = 0; r < 4; r++)
#pragma unroll
        for (int c = 0; c < 4; c++) acc[r][c] = 0.f;

    for (int kb = 0; kb < 128; kb += 64) {
        for (int i = tid; i < 2048; i += 256)
            ((float4*)Wsh)[i] = ((const float4*)(W + kb * 128))[i];
        for (int i = tid; i < 512; i += 256) {
            int r = i >> 4, c4 = i & 15;
            int row = row0 + r;
            float4 v = make_float4(0.f, 0.f, 0.f, 0.f);
            if (row < NN) v = *(const float4*)(x + (size_t)row * 128 + kb + c4 * 4);
            ((float4*)Xsh)[i] = v;
        }
        __syncthreads();
#pragma unroll 8
        for (int k = 0; k < 64; k++) {
            float4 wv = ((float4*)Wsh)[k * 32 + lane];
#pragma unroll
            for (int r = 0; r < 4; r++) {
                float xv = Xsh[(warp * 4 + r) * 64 + k];
                acc[r][0] = fmaf(xv, wv.x, acc[r][0]);
                acc[r][1] = fmaf(xv, wv.y, acc[r][1]);
                acc[r][2] = fmaf(xv, wv.z, acc[r][2]);
                acc[r][3] = fmaf(xv, wv.w, acc[r][3]);
            }
        }
        __syncthreads();
    }

    // epilogue: write h, compute alpha_s/alpha_d (per head = 4-lane group reduce)
    float4 a_s = ((const float4*)asr)[lane];
    float4 a_d = ((const float4*)adr)[lane];
#pragma unroll
    for (int r = 0; r < 4; r++) {
        int row = row0 + warp * 4 + r;
        if (row >= NN) continue;
        float4 v = make_float4(acc[r][0], acc[r][1], acc[r][2], acc[r][3]);
        ((float4*)(g_h + (size_t)row * 128))[lane] = v;
        float ps = v.x * a_s.x + v.y * a_s.y + v.z * a_s.z + v.w * a_s.w;
        float pd = v.x * a_d.x + v.y * a_d.y + v.z * a_d.z + v.w * a_d.w;
        ps += __shfl_down_sync(0xffffffffu, ps, 2);
        ps += __shfl_down_sync(0xffffffffu, ps, 1);
        pd += __shfl_down_sync(0xffffffffu, pd, 2);
        pd += __shfl_down_sync(0xffffffffu, pd, 1);
        if ((lane & 3) == 0) {
            g_as[row * 8 + (lane >> 2)] = ps;
            g_ad[row * 8 + (lane >> 2)] = pd;
        }
    }
}

// ---- zero accumulators + init global max ----
__global__ void prep() {
    int i = blockIdx.x * blockDim.x + threadIdx.x;
    if (i < NN * F / 4)
        ((float4*)g_acc)[i] = make_float4(0.f, 0.f, 0.f, 0.f);
    if (i < NN * 8) g_s[i] = 0.f;
    if (i < 8) g_gmax[i] = -INFINITY;
}

// ---- global per-head max of g_as (valid softmax shift upper bound) ----
__global__ void node_max() {
    __shared__ float sm[8][8];
    int tid = threadIdx.x, lane = tid & 31, warp = tid >> 5;
    float mx[8];
#pragma unroll
    for (int h = 0; h < 8; h++) mx[h] = -INFINITY;
    for (int n = blockIdx.x * blockDim.x + tid; n < NN; n += gridDim.x * blockDim.x) {
        float4 a0 = ((const float4*)g_as)[n * 2];
        float4 a1 = ((const float4*)g_as)[n * 2 + 1];
        mx[0] = fmaxf(mx[0], a0.x); mx[1] = fmaxf(mx[1], a0.y);
        mx[2] = fmaxf(mx[2], a0.z); mx[3] = fmaxf(mx[3], a0.w);
        mx[4] = fmaxf(mx[4], a1.x); mx[5] = fmaxf(mx[5], a1.y);
        mx[6] = fmaxf(mx[6], a1.z); mx[7] = fmaxf(mx[7], a1.w);
    }
#pragma unroll
    for (int off = 16; off >= 1; off >>= 1)
#pragma unroll
        for (int h = 0; h < 8; h++)
            mx[h] = fmaxf(mx[h], __shfl_xor_sync(0xffffffffu, mx[h], off));
    if (lane < 8) sm[warp][lane] = mx[lane];
    __syncthreads();
    if (tid < 8) {
        float v = -INFINITY;
#pragma unroll
        for (int w = 0; w < 8; w++) v = fmaxf(v, sm[w][tid]);
        atomicMaxF(&g_gmax[tid], v);
    }
}

// ---- fused edge pass: score -> exp -> denom atomics -> weighted scatter ----
// one warp per edge; lane owns 4 channels; head = lane>>2
__global__ void aggregate(const int* __restrict__ ei) {
    int gw   = (int)((blockIdx.x * (size_t)blockDim.x + threadIdx.x) >> 5);
    int lane = threadIdx.x & 31;
    if (gw >= ETOT) return;
    int s, d;
    if (gw < NEDGE) { s = ei[gw]; d = ei[NEDGE + gw]; } else { s = gw - NEDGE; d = s; }
    int head = lane >> 2;
    float asv = g_as[s * 8 + head];
    float adv = g_ad[d * 8 + head];
    float mp  = lrelu(g_gmax[head] + adv);     // per-(d,h) shift, >= all edge scores into d
    float w   = __expf(lrelu(asv + adv) - mp);
    if ((lane & 3) == 0) atomicAdd(g_s + d * 8 + head, w);
    float4 hv = ((const float4*)(g_h + (size_t)s * 128))[lane];
    float4 v = make_float4(hv.x * w, hv.y * w, hv.z * w, hv.w * w);
    float* out = g_acc + (size_t)d * 128 + lane * 4;
    asm volatile("red.global.add.v4.f32 [%0], {%1,%2,%3,%4};"
                 :: "l"(out), "f"(v.x), "f"(v.y), "f"(v.z), "f"(v.w)
                 : "memory");
}

// ---- normalize + bias + elu ----
__global__ void bias_act(const float* __restrict__ bias, float* __restrict__ out, int to_x2) {
    int i = blockIdx.x * blockDim.x + threadIdx.x;   // float4 index over NN*32
    if (i >= NN * 32) return;
    int node = i >> 5, c4 = i & 31, head = c4 >> 2;
    float inv = 1.f / (g_s[node * 8 + head] + 1e-16f);
    float4 v = ((float4*)g_acc)[i];
    float4 b = ((const float4*)bias)[c4];
    v.x = v.x * inv + b.x; v.y = v.y * inv + b.y;
    v.z = v.z * inv + b.z; v.w = v.w * inv + b.w;
    v.x = v.x > 0.f ? v.x : expm1f(v.x);
    v.y = v.y > 0.f ? v.y : expm1f(v.y);
    v.z = v.z > 0.f ? v.z : expm1f(v.z);
    v.w = v.w > 0.f ? v.w : expm1f(v.w);
    if (to_x2) ((float4*)g_x2)[i] = v;
    else       ((float4*)out)[i] = v;
}

extern "C" void kernel_launch(void* const* d_in, const int* in_sizes, int n_in,
                              void* d_out, int out_size) {
    const float* x   = (const float*)d_in[0];
    const int*   ei  = (const int*)d_in[1];
    const float* W1  = (const float*)d_in[2];
    const float* as1 = (const float*)d_in[3];
    const float* ad1 = (const float*)d_in[4];
    const float* b1  = (const float*)d_in[5];
    const float* W2  = (const float*)d_in[6];
    const float* as2 = (const float*)d_in[7];
    const float* ad2 = (const float*)d_in[8];
    const float* b2  = (const float*)d_in[9];
    float* out = (float*)d_out;

    const int GB   = (NN + 31) / 32;
    const int PB   = (NN * F / 4 + 255) / 256;
    const int NBF4 = (NN * 32 + 255) / 256;
    const int AGB  = (int)(((size_t)ETOT * 32 + 255) / 256);

    for (int layer = 0; layer < 2; layer++) {
        gemm_alpha<<<GB, 256>>>(x, layer,
                                layer ? W2 : W1,
                                layer ? as2 : as1,
                                layer ? ad2 : ad1);
        prep<<<PB, 256>>>();
        node_max<<<256, 256>>>();
        aggregate<<<AGB, 256>>>(ei);
        bias_act<<<NBF4, 256>>>(layer ? b2 : b1, out, layer == 0);
    }
}

// round 5
// speedup vs baseline: 1.9066x; 1.9066x over previous
#include <cuda_runtime.h>
#include <math.h>

#define NN 50000
#define NEDGE 800000
#define F 128
#define SCAN_T 1024
#define CHUNK ((NN + SCAN_T - 1) / SCAN_T)

// ---- scratch (static device globals; no allocation anywhere) ----
__device__ float g_h[(size_t)NN * F];     // transformed features
__device__ float g_x2[(size_t)NN * F];    // layer-2 input
__device__ float g_as[NN * 8];            // alpha_src per node/head
__device__ float g_ad[NN * 8];            // alpha_dst per node/head
__device__ float g_gmax[8];               // global per-head max of g_as
__device__ int   g_cnt[NN];               // in-degree counts
__device__ int   g_off[NN + 1];           // CSR offsets (by dst)
__device__ int   g_cur[NN];               // scatter cursors
__device__ int   g_csrc[NEDGE];           // CSR src indices

__device__ __forceinline__ float lrelu(float v) { return v >= 0.f ? v : 0.2f * v; }

__device__ __forceinline__ void atomicMaxF(float* a, float v) {
    if (v >= 0.f) atomicMax((int*)a, __float_as_int(v));
    else          atomicMin((unsigned int*)a, __float_as_uint(v));
}

// ================= CSR build (once per launch, shared by both layers) ========
__global__ void zero_cnt() {
    int i = blockIdx.x * blockDim.x + threadIdx.x;
    if (i < NN) g_cnt[i] = 0;
}

__global__ void count_edges(const int* __restrict__ ei) {
    int e = blockIdx.x * blockDim.x + threadIdx.x;
    if (e < NEDGE) atomicAdd(&g_cnt[ei[NEDGE + e]], 1);
}

__global__ void scan_offsets() {
    __shared__ int partial[SCAN_T];
    int t = threadIdx.x;
    int start = t * CHUNK;
    int end = min(start + CHUNK, NN);
    int s = 0;
    for (int i = start; i < end; i++) s += g_cnt[i];
    partial[t] = s;
    __syncthreads();
    for (int off = 1; off < SCAN_T; off <<= 1) {
        int v = (t >= off) ? partial[t - off] : 0;
        __syncthreads();
        partial[t] += v;
        __syncthreads();
    }
    int run = partial[t] - s;   // exclusive prefix at chunk start
    for (int i = start; i < end; i++) {
        g_off[i] = run;
        g_cur[i] = run;
        run += g_cnt[i];
    }
    if (t == SCAN_T - 1) g_off[NN] = partial[SCAN_T - 1];
}

__global__ void scatter_edges(const int* __restrict__ ei) {
    int e = blockIdx.x * blockDim.x + threadIdx.x;
    if (e >= NEDGE) return;
    int s = ei[e], d = ei[NEDGE + e];
    int pos = atomicAdd(&g_cur[d], 1);
    g_csrc[pos] = s;
}

// ================= GEMM h = x @ W, fused alpha epilogue ======================
// block = 256 threads (8 warps), 32 rows/block, 4 rows/warp, 4 cols/lane
__global__ void gemm_alpha(const float* __restrict__ xin, int use_x2,
                           const float* __restrict__ W,
                           const float* __restrict__ asr,
                           const float* __restrict__ adr)
{
    const float* x = use_x2 ? g_x2 : xin;
    __shared__ float Wsh[64 * 128];
    __shared__ float Xsh[32 * 64];
    int tid  = threadIdx.x;
    int warp = tid >> 5, lane = tid & 31;
    int row0 = blockIdx.x * 32;
    float acc[4][4];
#pragma unroll
    for (int r = 0; r < 4; r++)
#pragma unroll
        for (int c = 0; c < 4; c++) acc[r][c] = 0.f;

    for (int kb = 0; kb < 128; kb += 64) {
        for (int i = tid; i < 2048; i += 256)
            ((float4*)Wsh)[i] = ((const float4*)(W + kb * 128))[i];
        for (int i = tid; i < 512; i += 256) {
            int r = i >> 4, c4 = i & 15;
            int row = row0 + r;
            float4 v = make_float4(0.f, 0.f, 0.f, 0.f);
            if (row < NN) v = *(const float4*)(x + (size_t)row * 128 + kb + c4 * 4);
            ((float4*)Xsh)[i] = v;
        }
        __syncthreads();
#pragma unroll 8
        for (int k = 0; k < 64; k++) {
            float4 wv = ((float4*)Wsh)[k * 32 + lane];
#pragma unroll
            for (int r = 0; r < 4; r++) {
                float xv = Xsh[(warp * 4 + r) * 64 + k];
                acc[r][0] = fmaf(xv, wv.x, acc[r][0]);
                acc[r][1] = fmaf(xv, wv.y, acc[r][1]);
                acc[r][2] = fmaf(xv, wv.z, acc[r][2]);
                acc[r][3] = fmaf(xv, wv.w, acc[r][3]);
            }
        }
        __syncthreads();
    }

    float4 a_s = ((const float4*)asr)[lane];
    float4 a_d = ((const float4*)adr)[lane];
#pragma unroll
    for (int r = 0; r < 4; r++) {
        int row = row0 + warp * 4 + r;
        if (row >= NN) continue;
        float4 v = make_float4(acc[r][0], acc[r][1], acc[r][2], acc[r][3]);
        ((float4*)(g_h + (size_t)row * 128))[lane] = v;
        float ps = v.x * a_s.x + v.y * a_s.y + v.z * a_s.z + v.w * a_s.w;
        float pd = v.x * a_d.x + v.y * a_d.y + v.z * a_d.z + v.w * a_d.w;
        ps += __shfl_down_sync(0xffffffffu, ps, 2);
        ps += __shfl_down_sync(0xffffffffu, ps, 1);
        pd += __shfl_down_sync(0xffffffffu, pd, 2);
        pd += __shfl_down_sync(0xffffffffu, pd, 1);
        if ((lane & 3) == 0) {
            g_as[row * 8 + (lane >> 2)] = ps;
            g_ad[row * 8 + (lane >> 2)] = pd;
        }
    }
}

// ================= global per-head max of g_as ===============================
__global__ void init_gmax() {
    if (threadIdx.x < 8) g_gmax[threadIdx.x] = -INFINITY;
}

__global__ void node_max() {
    __shared__ float sm[8][8];
    int tid = threadIdx.x, lane = tid & 31, warp = tid >> 5;
    float mx[8];
#pragma unroll
    for (int h = 0; h < 8; h++) mx[h] = -INFINITY;
    for (int n = blockIdx.x * blockDim.x + tid; n < NN; n += gridDim.x * blockDim.x) {
        float4 a0 = ((const float4*)g_as)[n * 2];
        float4 a1 = ((const float4*)g_as)[n * 2 + 1];
        mx[0] = fmaxf(mx[0], a0.x); mx[1] = fmaxf(mx[1], a0.y);
        mx[2] = fmaxf(mx[2], a0.z); mx[3] = fmaxf(mx[3], a0.w);
        mx[4] = fmaxf(mx[4], a1.x); mx[5] = fmaxf(mx[5], a1.y);
        mx[6] = fmaxf(mx[6], a1.z); mx[7] = fmaxf(mx[7], a1.w);
    }
#pragma unroll
    for (int off = 16; off >= 1; off >>= 1)
#pragma unroll
        for (int h = 0; h < 8; h++)
            mx[h] = fmaxf(mx[h], __shfl_xor_sync(0xffffffffu, mx[h], off));
    if (lane < 8) sm[warp][lane] = mx[lane];
    __syncthreads();
    if (tid < 8) {
        float v = -INFINITY;
#pragma unroll
        for (int w = 0; w < 8; w++) v = fmaxf(v, sm[w][tid]);
        atomicMaxF(&g_gmax[tid], v);
    }
}

// ================= gather aggregation (warp per dst node) ====================
// lane owns 4 channels (head = lane>>2); register accumulation; no atomics.
// Fused: softmax (shifted), normalize, +bias, ELU, output write.
__global__ void gat_gather(const float* __restrict__ bias,
                           float* __restrict__ out, int to_x2)
{
    int d    = (int)((blockIdx.x * (size_t)blockDim.x + threadIdx.x) >> 5);
    int lane = threadIdx.x & 31;
    if (d >= NN) return;
    int head = lane >> 2;

    float adv = g_ad[d * 8 + head];
    float mp  = lrelu(g_gmax[head] + adv);   // >= every edge score into d

    // self-loop contribution
    float w = __expf(lrelu(g_as[d * 8 + head] + adv) - mp);
    float4 hv = ((const float4*)(g_h + (size_t)d * 128))[lane];
    float denom = w;
    float4 acc = make_float4(w * hv.x, w * hv.y, w * hv.z, w * hv.w);

    int e  = g_off[d];
    int e1 = g_off[d + 1];
    // unroll x2 for memory-level parallelism on the src->as/h chains
    for (; e + 1 < e1; e += 2) {
        int s0 = g_csrc[e];
        int s1 = g_csrc[e + 1];
        float a0 = g_as[s0 * 8 + head];
        float a1 = g_as[s1 * 8 + head];
        float4 h0 = ((const float4*)(g_h + (size_t)s0 * 128))[lane];
        float4 h1 = ((const float4*)(g_h + (size_t)s1 * 128))[lane];
        float w0 = __expf(lrelu(a0 + adv) - mp);
        float w1 = __expf(lrelu(a1 + adv) - mp);
        denom += w0 + w1;
        acc.x = fmaf(w0, h0.x, acc.x); acc.y = fmaf(w0, h0.y, acc.y);
        acc.z = fmaf(w0, h0.z, acc.z); acc.w = fmaf(w0, h0.w, acc.w);
        acc.x = fmaf(w1, h1.x, acc.x); acc.y = fmaf(w1, h1.y, acc.y);
        acc.z = fmaf(w1, h1.z, acc.z); acc.w = fmaf(w1, h1.w, acc.w);
    }
    if (e < e1) {
        int s0 = g_csrc[e];
        float a0 = g_as[s0 * 8 + head];
        float4 h0 = ((const float4*)(g_h + (size_t)s0 * 128))[lane];
        float w0 = __expf(lrelu(a0 + adv) - mp);
        denom += w0;
        acc.x = fmaf(w0, h0.x, acc.x); acc.y = fmaf(w0, h0.y, acc.y);
        acc.z = fmaf(w0, h0.z, acc.z); acc.w = fmaf(w0, h0.w, acc.w);
    }

    float inv = 1.f / (denom + 1e-16f);
    float4 b = ((const float4*)bias)[lane];
    float4 v;
    v.x = acc.x * inv + b.x; v.y = acc.y * inv + b.y;
    v.z = acc.z * inv + b.z; v.w = acc.w * inv + b.w;
    v.x = v.x > 0.f ? v.x : expm1f(v.x);
    v.y = v.y > 0.f ? v.y : expm1f(v.y);
    v.z = v.z > 0.f ? v.z : expm1f(v.z);
    v.w = v.w > 0.f ? v.w : expm1f(v.w);
    float4* dst = to_x2 ? (float4*)(g_x2 + (size_t)d * 128)
                        : (float4*)(out + (size_t)d * 128);
    dst[lane] = v;
}

extern "C" void kernel_launch(void* const* d_in, const int* in_sizes, int n_in,
                              void* d_out, int out_size) {
    const float* x   = (const float*)d_in[0];
    const int*   ei  = (const int*)d_in[1];
    const float* W1  = (const float*)d_in[2];
    const float* as1 = (const float*)d_in[3];
    const float* ad1 = (const float*)d_in[4];
    const float* b1  = (const float*)d_in[5];
    const float* W2  = (const float*)d_in[6];
    const float* as2 = (const float*)d_in[7];
    const float* ad2 = (const float*)d_in[8];
    const float* b2  = (const float*)d_in[9];
    float* out = (float*)d_out;

    const int GB = (NN + 31) / 32;
    const int NB = (NN + 255) / 256;
    const int EB = (NEDGE + 255) / 256;
    const int AG = (int)(((size_t)NN * 32 + 255) / 256);

    // CSR build (shared by both layers)
    zero_cnt<<<NB, 256>>>();
    count_edges<<<EB, 256>>>(ei);
    scan_offsets<<<1, SCAN_T>>>();
    scatter_edges<<<EB, 256>>>(ei);

    for (int layer = 0; layer < 2; layer++) {
        gemm_alpha<<<GB, 256>>>(x, layer,
                                layer ? W2 : W1,
                                layer ? as2 : as1,
                                layer ? ad2 : ad1);
        init_gmax<<<1, 32>>>();
        node_max<<<256, 256>>>();
        gat_gather<<<AG, 256>>>(layer ? b2 : b1, out, layer == 0);
    }
}